// round 8
// baseline (speedup 1.0000x reference)
#include <cuda_runtime.h>
#include <cuda_fp16.h>

#define NB 4
#define NQ 128
#define NK 1024
#define HD 256
#define DV 256

// Scratch (device globals — no allocation allowed)
__device__ float g_qp[NB * NQ * HD];      // 512 KB projected queries
__device__ float g_kp[NB * NK * HD];      // 4 MB projected keys
__device__ float g_scores[NB * NQ * NK];  // 2 MB scores -> probs (in place)

__device__ __forceinline__ __half2 tanh2(__half2 x) {
    unsigned xi = *(unsigned*)&x, yi;
    asm("tanh.approx.f16x2 %0, %1;" : "=r"(yi) : "r"(xi));
    return *(__half2*)&yi;
}

// -------------------------------------------------------------------------
// Fused projections: g_qp = Q @ Wq^T (grid.y 0..7), g_kp = K @ Wk^T (8..71).
// Tiled 64x64, 256 threads, 4x4 per thread, scalar FFMA.
// Smem depth-major [16][68]: inner loads are two conflict-free float4 LDS.
// -------------------------------------------------------------------------
__global__ __launch_bounds__(256) void proj_kernel(
    const float* __restrict__ Q, const float* __restrict__ K,
    const float* __restrict__ Wq, const float* __restrict__ Wk)
{
    __shared__ float Xt[16][68];   // [depth][row]
    __shared__ float Wt[16][68];   // [depth][col]

    const int by = blockIdx.y;
    const float* X;
    const float* W;
    float* out;
    int r0;
    if (by < 8) { X = Q; W = Wq; out = g_qp; r0 = by * 64; }
    else        { X = K; W = Wk; out = g_kp; r0 = (by - 8) * 64; }

    const int h0 = blockIdx.x * 64;
    const int tid = threadIdx.x;
    const int tx = tid & 15;
    const int ty = tid >> 4;

    const int lr = tid >> 2;        // 0..63
    const int lc = (tid & 3) * 4;   // 0,4,8,12

    float acc[4][4] = {};

    for (int d0 = 0; d0 < HD; d0 += 16) {
        float4 xv = *(const float4*)&X[(size_t)(r0 + lr) * HD + d0 + lc];
        float4 wt = *(const float4*)&W[(size_t)(h0 + lr) * HD + d0 + lc];
        Xt[lc + 0][lr] = xv.x; Xt[lc + 1][lr] = xv.y;
        Xt[lc + 2][lr] = xv.z; Xt[lc + 3][lr] = xv.w;
        Wt[lc + 0][lr] = wt.x; Wt[lc + 1][lr] = wt.y;
        Wt[lc + 2][lr] = wt.z; Wt[lc + 3][lr] = wt.w;
        __syncthreads();

        #pragma unroll
        for (int dd = 0; dd < 16; dd++) {
            float4 xr = *(const float4*)&Xt[dd][ty * 4];
            float4 wr = *(const float4*)&Wt[dd][tx * 4];
            float xa[4] = {xr.x, xr.y, xr.z, xr.w};
            float wa[4] = {wr.x, wr.y, wr.z, wr.w};
            #pragma unroll
            for (int i = 0; i < 4; i++)
                #pragma unroll
                for (int j = 0; j < 4; j++)
                    acc[i][j] += xa[i] * wa[j];
        }
        __syncthreads();
    }

    #pragma unroll
    for (int i = 0; i < 4; i++)
        *(float4*)&out[(size_t)(r0 + ty * 4 + i) * HD + h0 + tx * 4] =
            make_float4(acc[i][0], acc[i][1], acc[i][2], acc[i][3]);
}

// -------------------------------------------------------------------------
// Scores: s[b,q,k] = sum_h wv[h] * tanh(qp[b,q,h] + kp[b,k,h])
// f16x2 path: one MUFU per TWO h-channels (hypothesis under test).
// Structure identical to R7 winner: 128 thr, 8q x 64k, 16-key warp strips,
// grid (16,16,4) = 1024 blocks, vlen warp skip, k prefetch.
// -------------------------------------------------------------------------
__global__ __launch_bounds__(128) void scores_kernel(
    const float* __restrict__ wv, const int* __restrict__ valid_lens)
{
    const int b  = blockIdx.z;
    const int q0 = blockIdx.y * 8;
    const int k0 = blockIdx.x * 64;
    const int warp = threadIdx.x >> 5;
    const int lane = threadIdx.x & 31;
    const int hbase = lane * 8;

    const int vlen = valid_lens[b];
    const int kw0 = k0 + warp * 16;
    int nit = vlen - kw0;
    if (nit <= 0) return;          // whole strip masked
    if (nit > 16) nit = 16;

    __half2 qh[8][4];
    const float* qbase = g_qp + (size_t)(b * NQ + q0) * HD + hbase;
    #pragma unroll
    for (int j = 0; j < 8; j++) {
        float4 a = *(const float4*)(qbase + j * HD);
        float4 c = *(const float4*)(qbase + j * HD + 4);
        qh[j][0] = __floats2half2_rn(a.x, a.y);
        qh[j][1] = __floats2half2_rn(a.z, a.w);
        qh[j][2] = __floats2half2_rn(c.x, c.y);
        qh[j][3] = __floats2half2_rn(c.z, c.w);
    }

    __half2 wh[4];
    {
        float4 a = *(const float4*)(wv + hbase);
        float4 c = *(const float4*)(wv + hbase + 4);
        wh[0] = __floats2half2_rn(a.x, a.y);
        wh[1] = __floats2half2_rn(a.z, a.w);
        wh[2] = __floats2half2_rn(c.x, c.y);
        wh[3] = __floats2half2_rn(c.z, c.w);
    }

    const float* kbase = g_kp + (size_t)b * NK * HD + hbase;

    float4 ka = *(const float4*)(kbase + (size_t)kw0 * HD);
    float4 kc = *(const float4*)(kbase + (size_t)kw0 * HD + 4);

    for (int it = 0; it < nit; it++) {
        float4 na, nc;
        if (it + 1 < nit) {
            const float* np = kbase + (size_t)(kw0 + it + 1) * HD;
            na = *(const float4*)np;
            nc = *(const float4*)(np + 4);
        }

        __half2 kh[4];
        kh[0] = __floats2half2_rn(ka.x, ka.y);
        kh[1] = __floats2half2_rn(ka.z, ka.w);
        kh[2] = __floats2half2_rn(kc.x, kc.y);
        kh[3] = __floats2half2_rn(kc.z, kc.w);

        float acc[8];
        #pragma unroll
        for (int j = 0; j < 8; j++) {
            __half2 t0 = tanh2(__hadd2(qh[j][0], kh[0]));
            __half2 t1 = tanh2(__hadd2(qh[j][1], kh[1]));
            __half2 t2 = tanh2(__hadd2(qh[j][2], kh[2]));
            __half2 t3 = tanh2(__hadd2(qh[j][3], kh[3]));
            __half2 p0 = __hmul2(t0, wh[0]);
            __half2 p1 = __hmul2(t1, wh[1]);
            __half2 p2 = __hmul2(t2, wh[2]);
            __half2 p3 = __hmul2(t3, wh[3]);
            __half2 r = __hadd2(__hadd2(p0, p1), __hadd2(p2, p3));
            float2 f = __half22float2(r);
            acc[j] = f.x + f.y;
        }

        #pragma unroll
        for (int j = 0; j < 8; j++) {
            float v = acc[j];
            v += __shfl_xor_sync(0xFFFFFFFFu, v, 16);
            v += __shfl_xor_sync(0xFFFFFFFFu, v, 8);
            v += __shfl_xor_sync(0xFFFFFFFFu, v, 4);
            v += __shfl_xor_sync(0xFFFFFFFFu, v, 2);
            v += __shfl_xor_sync(0xFFFFFFFFu, v, 1);
            if (lane == 0)
                g_scores[(size_t)(b * NQ + q0 + j) * NK + kw0 + it] = v;
        }

        ka = na; kc = nc;
    }
}

// -------------------------------------------------------------------------
// Masked softmax over each 1024-long score row, in place.
// Also zeroes this row's 256-float output slice (AV accumulates atomically).
// One 256-thread block per row. Grid: NB*NQ = 512 blocks.
// -------------------------------------------------------------------------
__global__ __launch_bounds__(256) void softmax_kernel(
    const int* __restrict__ valid_lens, float* __restrict__ out)
{
    __shared__ float red[8];

    const int row = blockIdx.x;             // 0..511
    const int b   = row >> 7;
    const int tid = threadIdx.x;
    const int warp = tid >> 5;
    const int lane = tid & 31;
    const int vlen = valid_lens[b];

    // zero this row's output slice (before av_kernel runs)
    out[(size_t)row * DV + tid] = 0.f;

    float* rp = g_scores + (size_t)row * NK + tid * 4;

    float4 v = *(const float4*)rp;
    const int kb = tid * 4;
    if (kb + 0 >= vlen) v.x = -1e6f;
    if (kb + 1 >= vlen) v.y = -1e6f;
    if (kb + 2 >= vlen) v.z = -1e6f;
    if (kb + 3 >= vlen) v.w = -1e6f;

    float mx = fmaxf(fmaxf(v.x, v.y), fmaxf(v.z, v.w));
    #pragma unroll
    for (int off = 16; off; off >>= 1)
        mx = fmaxf(mx, __shfl_xor_sync(0xFFFFFFFFu, mx, off));
    if (lane == 0) red[warp] = mx;
    __syncthreads();
    if (warp == 0) {
        float m = red[lane & 7];
        #pragma unroll
        for (int off = 4; off; off >>= 1)
            m = fmaxf(m, __shfl_xor_sync(0xFFFFFFFFu, m, off));
        if (lane == 0) red[0] = m;
    }
    __syncthreads();
    mx = red[0];
    __syncthreads();

    float4 e;
    e.x = __expf(v.x - mx); e.y = __expf(v.y - mx);
    e.z = __expf(v.z - mx); e.w = __expf(v.w - mx);
    float sum = e.x + e.y + e.z + e.w;
    #pragma unroll
    for (int off = 16; off; off >>= 1)
        sum += __shfl_xor_sync(0xFFFFFFFFu, sum, off);
    if (lane == 0) red[warp] = sum;
    __syncthreads();
    if (warp == 0) {
        float s = red[lane & 7];
        #pragma unroll
        for (int off = 4; off; off >>= 1)
            s += __shfl_xor_sync(0xFFFFFFFFu, s, off);
        if (lane == 0) red[0] = s;
    }
    __syncthreads();
    const float inv = 1.0f / red[0];

    e.x *= inv; e.y *= inv; e.z *= inv; e.w *= inv;
    *(float4*)rp = e;
}

// -------------------------------------------------------------------------
// AV GEMM with split-K: out[r][v] += sum_k P[r][k] * V[b][k][v]
// Tile: 32 rows x 64 vdims, K-chunk 64 per block (split-K = 16).
// 256 threads, 2x4 outputs/thread, atomicAdd epilogue.
// Chunks entirely beyond valid_len skipped (their probs are exactly 0).
// Grid: (DV/64=4, rows/32=16, KSPLIT=16) = 1024 blocks (~7/SM).
// -------------------------------------------------------------------------
__global__ __launch_bounds__(256) void av_kernel(
    const float* __restrict__ V, const int* __restrict__ valid_lens,
    float* __restrict__ out)
{
    __shared__ float Ps[32][17];
    __shared__ float Vs[16][68];

    const int v0 = blockIdx.x * 64;
    const int r0 = blockIdx.y * 32;          // global row (b*NQ + q)
    const int b  = r0 >> 7;
    const int kz = blockIdx.z * 64;

    if (kz >= valid_lens[b]) return;         // probs exactly zero here

    const int tid = threadIdx.x;
    const int tx = tid & 15;
    const int ty = tid >> 4;                 // 0..15

    // Ps loaders: threads 0..127, 32 rows x 16 k
    const int plr = (tid & 127) >> 2;        // 0..31
    const int plc = (tid & 3) * 4;           // 0,4,8,12
    // Vs loaders: all 256 threads, 16 rows x 64 cols
    const int vlr = tid >> 4;                // 0..15
    const int vlc = (tid & 15) * 4;          // 0..60

    const float* Vb = V + (size_t)b * NK * DV;

    float acc[2][4] = {};

    for (int k0 = kz; k0 < kz + 64; k0 += 16) {
        if (tid < 128) {
            float4 pv = *(const float4*)&g_scores[(size_t)(r0 + plr) * NK + k0 + plc];
            Ps[plr][plc + 0] = pv.x; Ps[plr][plc + 1] = pv.y;
            Ps[plr][plc + 2] = pv.z; Ps[plr][plc + 3] = pv.w;
        }
        float4 vv = *(const float4*)&Vb[(size_t)(k0 + vlr) * DV + v0 + vlc];
        Vs[vlr][vlc + 0] = vv.x; Vs[vlr][vlc + 1] = vv.y;
        Vs[vlr][vlc + 2] = vv.z; Vs[vlr][vlc + 3] = vv.w;
        __syncthreads();

        #pragma unroll
        for (int dd = 0; dd < 16; dd++) {
            float pr[2], vr[4];
            pr[0] = Ps[ty * 2 + 0][dd];
            pr[1] = Ps[ty * 2 + 1][dd];
            #pragma unroll
            for (int j = 0; j < 4; j++) vr[j] = Vs[dd][tx * 4 + j];
            #pragma unroll
            for (int i = 0; i < 2; i++)
                #pragma unroll
                for (int j = 0; j < 4; j++)
                    acc[i][j] += pr[i] * vr[j];
        }
        __syncthreads();
    }

    #pragma unroll
    for (int i = 0; i < 2; i++)
        #pragma unroll
        for (int j = 0; j < 4; j++)
            atomicAdd(&out[(size_t)(r0 + ty * 2 + i) * DV + v0 + tx * 4 + j],
                      acc[i][j]);
}

// -------------------------------------------------------------------------
extern "C" void kernel_launch(void* const* d_in, const int* in_sizes, int n_in,
                              void* d_out, int out_size)
{
    const float* queries = (const float*)d_in[0];
    const float* keys    = (const float*)d_in[1];
    const float* values  = (const float*)d_in[2];
    const int*   vlens   = (const int*)d_in[3];
    const float* Wq      = (const float*)d_in[4];
    const float* Wk      = (const float*)d_in[5];
    const float* wv      = (const float*)d_in[6];
    float* out = (float*)d_out;

    // fused q+k projection: grid.y 0..7 = q tiles, 8..71 = k tiles
    proj_kernel<<<dim3(4, 72), 256>>>(queries, keys, Wq, Wk);
    // scores (f16x2 tanh experiment, only k < valid_len)
    scores_kernel<<<dim3(16, 16, 4), 128>>>(wv, vlens);
    // masked softmax (in place) + zero output rows
    softmax_kernel<<<512, 256>>>(vlens, out);
    // AV GEMM, split-K=16, 32-row tiles, dead chunks skipped
    av_kernel<<<dim3(4, 16, 16), 256>>>(values, vlens, out);
}

// round 9
// speedup vs baseline: 1.1034x; 1.1034x over previous
#include <cuda_runtime.h>

#define NB 4
#define NQ 128
#define NK 1024
#define HD 256
#define DV 256

// Scratch (device globals — no allocation allowed)
__device__ float g_qp[NB * NQ * HD];      // 512 KB projected queries
__device__ float g_kp[NB * NK * HD];      // 4 MB projected keys
__device__ float g_scores[NB * NQ * NK];  // 2 MB scores -> probs (in place)

__device__ __forceinline__ float tanh_fast(float x) {
    float y;
    asm("tanh.approx.f32 %0, %1;" : "=f"(y) : "f"(x));
    return y;
}

// -------------------------------------------------------------------------
// Fused projections: g_qp = Q @ Wq^T (grid.y 0..7), g_kp = K @ Wk^T (8..71).
// K-tiles whose key range lies beyond valid_len[b] are skipped: scores reads
// g_kp only for k < vlen (incl. prefetch) and softmax masks the rest, so the
// stale region is never consumed.
// Tiled 64x64, 256 threads, 4x4 per thread, scalar FFMA.
// -------------------------------------------------------------------------
__global__ __launch_bounds__(256) void proj_kernel(
    const float* __restrict__ Q, const float* __restrict__ K,
    const float* __restrict__ Wq, const float* __restrict__ Wk,
    const int* __restrict__ valid_lens)
{
    __shared__ float Xt[16][68];   // [depth][row]
    __shared__ float Wt[16][68];   // [depth][col]

    const int by = blockIdx.y;
    const float* X;
    const float* W;
    float* out;
    int r0;
    if (by < 8) { X = Q; W = Wq; out = g_qp; r0 = by * 64; }
    else {
        const int t = by - 8;              // 0..63 over 4096 key rows
        const int b = t >> 4;              // batch
        const int k0l = (t & 15) * 64;     // key offset within batch
        if (k0l >= valid_lens[b]) return;  // dead keys: never read downstream
        X = K; W = Wk; out = g_kp; r0 = t * 64;
    }

    const int h0 = blockIdx.x * 64;
    const int tid = threadIdx.x;
    const int tx = tid & 15;
    const int ty = tid >> 4;

    const int lr = tid >> 2;        // 0..63
    const int lc = (tid & 3) * 4;   // 0,4,8,12

    float acc[4][4] = {};

    for (int d0 = 0; d0 < HD; d0 += 16) {
        float4 xv = *(const float4*)&X[(size_t)(r0 + lr) * HD + d0 + lc];
        float4 wt = *(const float4*)&W[(size_t)(h0 + lr) * HD + d0 + lc];
        Xt[lc + 0][lr] = xv.x; Xt[lc + 1][lr] = xv.y;
        Xt[lc + 2][lr] = xv.z; Xt[lc + 3][lr] = xv.w;
        Wt[lc + 0][lr] = wt.x; Wt[lc + 1][lr] = wt.y;
        Wt[lc + 2][lr] = wt.z; Wt[lc + 3][lr] = wt.w;
        __syncthreads();

        #pragma unroll
        for (int dd = 0; dd < 16; dd++) {
            float4 xr = *(const float4*)&Xt[dd][ty * 4];
            float4 wr = *(const float4*)&Wt[dd][tx * 4];
            float xa[4] = {xr.x, xr.y, xr.z, xr.w};
            float wa[4] = {wr.x, wr.y, wr.z, wr.w};
            #pragma unroll
            for (int i = 0; i < 4; i++)
                #pragma unroll
                for (int j = 0; j < 4; j++)
                    acc[i][j] += xa[i] * wa[j];
        }
        __syncthreads();
    }

    #pragma unroll
    for (int i = 0; i < 4; i++)
        *(float4*)&out[(size_t)(r0 + ty * 4 + i) * HD + h0 + tx * 4] =
            make_float4(acc[i][0], acc[i][1], acc[i][2], acc[i][3]);
}

// -------------------------------------------------------------------------
// Scores: s[b,q,k] = sum_h wv[h] * tanh(qp[b,q,h] + kp[b,k,h])
// f32 tanh (proven at the MUFU floor). Only k < valid_len[b] computed.
// Block: 128 threads (4 warps), 8 queries x 64 keys (16-key warp strips).
// Grid: (16, 16, 4) = 1024 blocks.
// -------------------------------------------------------------------------
__global__ __launch_bounds__(128) void scores_kernel(
    const float* __restrict__ wv, const int* __restrict__ valid_lens)
{
    const int b  = blockIdx.z;
    const int q0 = blockIdx.y * 8;
    const int k0 = blockIdx.x * 64;
    const int warp = threadIdx.x >> 5;
    const int lane = threadIdx.x & 31;
    const int hbase = lane * 8;

    const int vlen = valid_lens[b];
    const int kw0 = k0 + warp * 16;
    int nit = vlen - kw0;
    if (nit <= 0) return;          // whole strip masked
    if (nit > 16) nit = 16;

    float qreg[8][8];
    const float* qbase = g_qp + (size_t)(b * NQ + q0) * HD + hbase;
    #pragma unroll
    for (int j = 0; j < 8; j++) {
        float4 a = *(const float4*)(qbase + j * HD);
        float4 c = *(const float4*)(qbase + j * HD + 4);
        qreg[j][0] = a.x; qreg[j][1] = a.y; qreg[j][2] = a.z; qreg[j][3] = a.w;
        qreg[j][4] = c.x; qreg[j][5] = c.y; qreg[j][6] = c.z; qreg[j][7] = c.w;
    }

    float wr[8];
    {
        float4 a = *(const float4*)(wv + hbase);
        float4 c = *(const float4*)(wv + hbase + 4);
        wr[0] = a.x; wr[1] = a.y; wr[2] = a.z; wr[3] = a.w;
        wr[4] = c.x; wr[5] = c.y; wr[6] = c.z; wr[7] = c.w;
    }

    const float* kbase = g_kp + (size_t)b * NK * HD + hbase;

    float4 ka = *(const float4*)(kbase + (size_t)kw0 * HD);
    float4 kc = *(const float4*)(kbase + (size_t)kw0 * HD + 4);

    for (int it = 0; it < nit; it++) {
        float4 na, nc;
        if (it + 1 < nit) {
            const float* np = kbase + (size_t)(kw0 + it + 1) * HD;
            na = *(const float4*)np;
            nc = *(const float4*)(np + 4);
        }

        float kr[8] = {ka.x, ka.y, ka.z, ka.w, kc.x, kc.y, kc.z, kc.w};

        float acc[8];
        #pragma unroll
        for (int j = 0; j < 8; j++) {
            float s = 0.f;
            #pragma unroll
            for (int i = 0; i < 8; i++)
                s += wr[i] * tanh_fast(qreg[j][i] + kr[i]);
            acc[j] = s;
        }

        #pragma unroll
        for (int j = 0; j < 8; j++) {
            float v = acc[j];
            v += __shfl_xor_sync(0xFFFFFFFFu, v, 16);
            v += __shfl_xor_sync(0xFFFFFFFFu, v, 8);
            v += __shfl_xor_sync(0xFFFFFFFFu, v, 4);
            v += __shfl_xor_sync(0xFFFFFFFFu, v, 2);
            v += __shfl_xor_sync(0xFFFFFFFFu, v, 1);
            if (lane == 0)
                g_scores[(size_t)(b * NQ + q0 + j) * NK + kw0 + it] = v;
        }

        ka = na; kc = nc;
    }
}

// -------------------------------------------------------------------------
// Masked softmax over each 1024-long score row, in place.
// Also zeroes this row's 256-float output slice (AV accumulates atomically).
// One 256-thread block per row. Grid: NB*NQ = 512 blocks.
// -------------------------------------------------------------------------
__global__ __launch_bounds__(256) void softmax_kernel(
    const int* __restrict__ valid_lens, float* __restrict__ out)
{
    __shared__ float red[8];

    const int row = blockIdx.x;             // 0..511
    const int b   = row >> 7;
    const int tid = threadIdx.x;
    const int warp = tid >> 5;
    const int lane = tid & 31;
    const int vlen = valid_lens[b];

    // zero this row's output slice (before av_kernel runs)
    out[(size_t)row * DV + tid] = 0.f;

    float* rp = g_scores + (size_t)row * NK + tid * 4;

    float4 v = *(const float4*)rp;
    const int kb = tid * 4;
    if (kb + 0 >= vlen) v.x = -1e6f;
    if (kb + 1 >= vlen) v.y = -1e6f;
    if (kb + 2 >= vlen) v.z = -1e6f;
    if (kb + 3 >= vlen) v.w = -1e6f;

    float mx = fmaxf(fmaxf(v.x, v.y), fmaxf(v.z, v.w));
    #pragma unroll
    for (int off = 16; off; off >>= 1)
        mx = fmaxf(mx, __shfl_xor_sync(0xFFFFFFFFu, mx, off));
    if (lane == 0) red[warp] = mx;
    __syncthreads();
    if (warp == 0) {
        float m = red[lane & 7];
        #pragma unroll
        for (int off = 4; off; off >>= 1)
            m = fmaxf(m, __shfl_xor_sync(0xFFFFFFFFu, m, off));
        if (lane == 0) red[0] = m;
    }
    __syncthreads();
    mx = red[0];
    __syncthreads();

    float4 e;
    e.x = __expf(v.x - mx); e.y = __expf(v.y - mx);
    e.z = __expf(v.z - mx); e.w = __expf(v.w - mx);
    float sum = e.x + e.y + e.z + e.w;
    #pragma unroll
    for (int off = 16; off; off >>= 1)
        sum += __shfl_xor_sync(0xFFFFFFFFu, sum, off);
    if (lane == 0) red[warp] = sum;
    __syncthreads();
    if (warp == 0) {
        float s = red[lane & 7];
        #pragma unroll
        for (int off = 4; off; off >>= 1)
            s += __shfl_xor_sync(0xFFFFFFFFu, s, off);
        if (lane == 0) red[0] = s;
    }
    __syncthreads();
    const float inv = 1.0f / red[0];

    e.x *= inv; e.y *= inv; e.z *= inv; e.w *= inv;
    *(float4*)rp = e;
}

// -------------------------------------------------------------------------
// AV GEMM with split-K: out[r][v] += sum_k P[r][k] * V[b][k][v]
// Tile: 32 rows x 64 vdims, K-chunk 64 per block (split-K = 16).
// 256 threads, 2x4 outputs/thread, atomicAdd epilogue.
// Chunks entirely beyond valid_len skipped (their probs are exactly 0).
// Grid: (DV/64=4, rows/32=16, KSPLIT=16) = 1024 blocks (~7/SM).
// -------------------------------------------------------------------------
__global__ __launch_bounds__(256) void av_kernel(
    const float* __restrict__ V, const int* __restrict__ valid_lens,
    float* __restrict__ out)
{
    __shared__ float Ps[32][17];
    __shared__ float Vs[16][68];

    const int v0 = blockIdx.x * 64;
    const int r0 = blockIdx.y * 32;          // global row (b*NQ + q)
    const int b  = r0 >> 7;
    const int kz = blockIdx.z * 64;

    if (kz >= valid_lens[b]) return;         // probs exactly zero here

    const int tid = threadIdx.x;
    const int tx = tid & 15;
    const int ty = tid >> 4;                 // 0..15

    // Ps loaders: threads 0..127, 32 rows x 16 k
    const int plr = (tid & 127) >> 2;        // 0..31
    const int plc = (tid & 3) * 4;           // 0,4,8,12
    // Vs loaders: all 256 threads, 16 rows x 64 cols
    const int vlr = tid >> 4;                // 0..15
    const int vlc = (tid & 15) * 4;          // 0..60

    const float* Vb = V + (size_t)b * NK * DV;

    float acc[2][4] = {};

    for (int k0 = kz; k0 < kz + 64; k0 += 16) {
        if (tid < 128) {
            float4 pv = *(const float4*)&g_scores[(size_t)(r0 + plr) * NK + k0 + plc];
            Ps[plr][plc + 0] = pv.x; Ps[plr][plc + 1] = pv.y;
            Ps[plr][plc + 2] = pv.z; Ps[plr][plc + 3] = pv.w;
        }
        float4 vv = *(const float4*)&Vb[(size_t)(k0 + vlr) * DV + v0 + vlc];
        Vs[vlr][vlc + 0] = vv.x; Vs[vlr][vlc + 1] = vv.y;
        Vs[vlr][vlc + 2] = vv.z; Vs[vlr][vlc + 3] = vv.w;
        __syncthreads();

        #pragma unroll
        for (int dd = 0; dd < 16; dd++) {
            float pr[2], vr[4];
            pr[0] = Ps[ty * 2 + 0][dd];
            pr[1] = Ps[ty * 2 + 1][dd];
            #pragma unroll
            for (int j = 0; j < 4; j++) vr[j] = Vs[dd][tx * 4 + j];
            #pragma unroll
            for (int i = 0; i < 2; i++)
                #pragma unroll
                for (int j = 0; j < 4; j++)
                    acc[i][j] += pr[i] * vr[j];
        }
        __syncthreads();
    }

    #pragma unroll
    for (int i = 0; i < 2; i++)
        #pragma unroll
        for (int j = 0; j < 4; j++)
            atomicAdd(&out[(size_t)(r0 + ty * 2 + i) * DV + v0 + tx * 4 + j],
                      acc[i][j]);
}

// -------------------------------------------------------------------------
extern "C" void kernel_launch(void* const* d_in, const int* in_sizes, int n_in,
                              void* d_out, int out_size)
{
    const float* queries = (const float*)d_in[0];
    const float* keys    = (const float*)d_in[1];
    const float* values  = (const float*)d_in[2];
    const int*   vlens   = (const int*)d_in[3];
    const float* Wq      = (const float*)d_in[4];
    const float* Wk      = (const float*)d_in[5];
    const float* wv      = (const float*)d_in[6];
    float* out = (float*)d_out;

    // fused q+k projection; k tiles beyond valid_len skipped
    proj_kernel<<<dim3(4, 72), 256>>>(queries, keys, Wq, Wk, vlens);
    // scores (f32 tanh, only k < valid_len)
    scores_kernel<<<dim3(16, 16, 4), 128>>>(wv, vlens);
    // masked softmax (in place) + zero output rows
    softmax_kernel<<<512, 256>>>(vlens, out);
    // AV GEMM, split-K=16, 32-row tiles, dead chunks skipped
    av_kernel<<<dim3(4, 16, 16), 256>>>(values, vlens, out);
}

// round 10
// speedup vs baseline: 1.1108x; 1.0067x over previous
#include <cuda_runtime.h>

#define NB 4
#define NQ 128
#define NK 1024
#define HD 256
#define DV 256

// Scratch (device globals — no allocation allowed)
__device__ float g_qp[NB * NQ * HD];      // 512 KB projected queries
__device__ float g_kp[NB * NK * HD];      // 4 MB projected keys
__device__ float g_scores[NB * NQ * NK];  // 2 MB scores -> probs (in place)

__device__ __forceinline__ float tanh_fast(float x) {
    float y;
    asm("tanh.approx.f32 %0, %1;" : "=f"(y) : "f"(x));
    return y;
}

#define FFMA2(d, a, b, c) \
    asm("fma.rn.f32x2 %0, %1, %2, %3;" : "=l"(d) : "l"(a), "l"(b), "l"(c))
#define PACK2(d, lo, hi) \
    asm("mov.b64 %0, {%1, %2};" : "=l"(d) : "f"(lo), "f"(hi))
#define UNPACK2(lo, hi, d) \
    asm("mov.b64 {%0, %1}, %2;" : "=f"(lo), "=f"(hi) : "l"(d))

// -------------------------------------------------------------------------
// Fused projections: g_qp = Q @ Wq^T (grid.y 0..7), g_kp = K @ Wk^T (8..71).
// Smem layout identical to the proven scalar version (depth-major [16][68]).
// Inner loop: packed fma.rn.f32x2. W pairs are adjacent floats in Wt (free
// ulonglong2 LDS); {x,x} broadcast pairs built with PACK MOVs on the ALU
// pipe, concurrent with the fma pipe. Single-variable FFMA2-rate experiment.
// -------------------------------------------------------------------------
__global__ __launch_bounds__(256) void proj_kernel(
    const float* __restrict__ Q, const float* __restrict__ K,
    const float* __restrict__ Wq, const float* __restrict__ Wk,
    const int* __restrict__ valid_lens)
{
    __shared__ float Xt[16][68];   // [depth][row]
    __shared__ float Wt[16][68];   // [depth][col]

    const int by = blockIdx.y;
    const float* X;
    const float* W;
    float* out;
    int r0;
    if (by < 8) { X = Q; W = Wq; out = g_qp; r0 = by * 64; }
    else {
        const int t = by - 8;              // 0..63 over 4096 key rows
        const int b = t >> 4;              // batch
        const int k0l = (t & 15) * 64;     // key offset within batch
        if (k0l >= valid_lens[b]) return;  // dead keys: never read downstream
        X = K; W = Wk; out = g_kp; r0 = t * 64;
    }

    const int h0 = blockIdx.x * 64;
    const int tid = threadIdx.x;
    const int tx = tid & 15;
    const int ty = tid >> 4;

    const int lr = tid >> 2;        // 0..63
    const int lc = (tid & 3) * 4;   // 0,4,8,12

    unsigned long long acc2[4][2] = {};

    for (int d0 = 0; d0 < HD; d0 += 16) {
        float4 xv = *(const float4*)&X[(size_t)(r0 + lr) * HD + d0 + lc];
        float4 wt = *(const float4*)&W[(size_t)(h0 + lr) * HD + d0 + lc];
        Xt[lc + 0][lr] = xv.x; Xt[lc + 1][lr] = xv.y;
        Xt[lc + 2][lr] = xv.z; Xt[lc + 3][lr] = xv.w;
        Wt[lc + 0][lr] = wt.x; Wt[lc + 1][lr] = wt.y;
        Wt[lc + 2][lr] = wt.z; Wt[lc + 3][lr] = wt.w;
        __syncthreads();

        #pragma unroll
        for (int dd = 0; dd < 16; dd++) {
            float4 xr = *(const float4*)&Xt[dd][ty * 4];
            // (w0,w1),(w2,w3) are adjacent 8B-aligned floats: free f32x2 pair
            ulonglong2 w = *(const ulonglong2*)&Wt[dd][tx * 4];
            float xa[4] = {xr.x, xr.y, xr.z, xr.w};
            #pragma unroll
            for (int i = 0; i < 4; i++) {
                unsigned long long xb;
                PACK2(xb, xa[i], xa[i]);            // ALU-pipe MOV
                FFMA2(acc2[i][0], xb, w.x, acc2[i][0]);
                FFMA2(acc2[i][1], xb, w.y, acc2[i][1]);
            }
        }
        __syncthreads();
    }

    #pragma unroll
    for (int i = 0; i < 4; i++) {
        float o0, o1, o2, o3;
        UNPACK2(o0, o1, acc2[i][0]);
        UNPACK2(o2, o3, acc2[i][1]);
        *(float4*)&out[(size_t)(r0 + ty * 4 + i) * HD + h0 + tx * 4] =
            make_float4(o0, o1, o2, o3);
    }
}

// -------------------------------------------------------------------------
// Scores: s[b,q,k] = sum_h wv[h] * tanh(qp[b,q,h] + kp[b,k,h])
// f32 tanh (proven at the MUFU floor). Only k < valid_len[b] computed.
// Block: 128 threads (4 warps), 8 queries x 64 keys (16-key warp strips).
// Grid: (16, 16, 4) = 1024 blocks.
// -------------------------------------------------------------------------
__global__ __launch_bounds__(128) void scores_kernel(
    const float* __restrict__ wv, const int* __restrict__ valid_lens)
{
    const int b  = blockIdx.z;
    const int q0 = blockIdx.y * 8;
    const int k0 = blockIdx.x * 64;
    const int warp = threadIdx.x >> 5;
    const int lane = threadIdx.x & 31;
    const int hbase = lane * 8;

    const int vlen = valid_lens[b];
    const int kw0 = k0 + warp * 16;
    int nit = vlen - kw0;
    if (nit <= 0) return;          // whole strip masked
    if (nit > 16) nit = 16;

    float qreg[8][8];
    const float* qbase = g_qp + (size_t)(b * NQ + q0) * HD + hbase;
    #pragma unroll
    for (int j = 0; j < 8; j++) {
        float4 a = *(const float4*)(qbase + j * HD);
        float4 c = *(const float4*)(qbase + j * HD + 4);
        qreg[j][0] = a.x; qreg[j][1] = a.y; qreg[j][2] = a.z; qreg[j][3] = a.w;
        qreg[j][4] = c.x; qreg[j][5] = c.y; qreg[j][6] = c.z; qreg[j][7] = c.w;
    }

    float wr[8];
    {
        float4 a = *(const float4*)(wv + hbase);
        float4 c = *(const float4*)(wv + hbase + 4);
        wr[0] = a.x; wr[1] = a.y; wr[2] = a.z; wr[3] = a.w;
        wr[4] = c.x; wr[5] = c.y; wr[6] = c.z; wr[7] = c.w;
    }

    const float* kbase = g_kp + (size_t)b * NK * HD + hbase;

    float4 ka = *(const float4*)(kbase + (size_t)kw0 * HD);
    float4 kc = *(const float4*)(kbase + (size_t)kw0 * HD + 4);

    for (int it = 0; it < nit; it++) {
        float4 na, nc;
        if (it + 1 < nit) {
            const float* np = kbase + (size_t)(kw0 + it + 1) * HD;
            na = *(const float4*)np;
            nc = *(const float4*)(np + 4);
        }

        float kr[8] = {ka.x, ka.y, ka.z, ka.w, kc.x, kc.y, kc.z, kc.w};

        float acc[8];
        #pragma unroll
        for (int j = 0; j < 8; j++) {
            float s = 0.f;
            #pragma unroll
            for (int i = 0; i < 8; i++)
                s += wr[i] * tanh_fast(qreg[j][i] + kr[i]);
            acc[j] = s;
        }

        #pragma unroll
        for (int j = 0; j < 8; j++) {
            float v = acc[j];
            v += __shfl_xor_sync(0xFFFFFFFFu, v, 16);
            v += __shfl_xor_sync(0xFFFFFFFFu, v, 8);
            v += __shfl_xor_sync(0xFFFFFFFFu, v, 4);
            v += __shfl_xor_sync(0xFFFFFFFFu, v, 2);
            v += __shfl_xor_sync(0xFFFFFFFFu, v, 1);
            if (lane == 0)
                g_scores[(size_t)(b * NQ + q0 + j) * NK + kw0 + it] = v;
        }

        ka = na; kc = nc;
    }
}

// -------------------------------------------------------------------------
// Masked softmax over each 1024-long score row, in place.
// Also zeroes this row's 256-float output slice (AV accumulates atomically).
// One 256-thread block per row. Grid: NB*NQ = 512 blocks.
// -------------------------------------------------------------------------
__global__ __launch_bounds__(256) void softmax_kernel(
    const int* __restrict__ valid_lens, float* __restrict__ out)
{
    __shared__ float red[8];

    const int row = blockIdx.x;             // 0..511
    const int b   = row >> 7;
    const int tid = threadIdx.x;
    const int warp = tid >> 5;
    const int lane = tid & 31;
    const int vlen = valid_lens[b];

    // zero this row's output slice (before av_kernel runs)
    out[(size_t)row * DV + tid] = 0.f;

    float* rp = g_scores + (size_t)row * NK + tid * 4;

    float4 v = *(const float4*)rp;
    const int kb = tid * 4;
    if (kb + 0 >= vlen) v.x = -1e6f;
    if (kb + 1 >= vlen) v.y = -1e6f;
    if (kb + 2 >= vlen) v.z = -1e6f;
    if (kb + 3 >= vlen) v.w = -1e6f;

    float mx = fmaxf(fmaxf(v.x, v.y), fmaxf(v.z, v.w));
    #pragma unroll
    for (int off = 16; off; off >>= 1)
        mx = fmaxf(mx, __shfl_xor_sync(0xFFFFFFFFu, mx, off));
    if (lane == 0) red[warp] = mx;
    __syncthreads();
    if (warp == 0) {
        float m = red[lane & 7];
        #pragma unroll
        for (int off = 4; off; off >>= 1)
            m = fmaxf(m, __shfl_xor_sync(0xFFFFFFFFu, m, off));
        if (lane == 0) red[0] = m;
    }
    __syncthreads();
    mx = red[0];
    __syncthreads();

    float4 e;
    e.x = __expf(v.x - mx); e.y = __expf(v.y - mx);
    e.z = __expf(v.z - mx); e.w = __expf(v.w - mx);
    float sum = e.x + e.y + e.z + e.w;
    #pragma unroll
    for (int off = 16; off; off >>= 1)
        sum += __shfl_xor_sync(0xFFFFFFFFu, sum, off);
    if (lane == 0) red[warp] = sum;
    __syncthreads();
    if (warp == 0) {
        float s = red[lane & 7];
        #pragma unroll
        for (int off = 4; off; off >>= 1)
            s += __shfl_xor_sync(0xFFFFFFFFu, s, off);
        if (lane == 0) red[0] = s;
    }
    __syncthreads();
    const float inv = 1.0f / red[0];

    e.x *= inv; e.y *= inv; e.z *= inv; e.w *= inv;
    *(float4*)rp = e;
}

// -------------------------------------------------------------------------
// AV GEMM with split-K: out[r][v] += sum_k P[r][k] * V[b][k][v]
// Tile: 32 rows x 64 vdims, K-chunk 64 per block (split-K = 16).
// 256 threads, 2x4 outputs/thread, atomicAdd epilogue.
// Chunks entirely beyond valid_len skipped (their probs are exactly 0).
// Grid: (DV/64=4, rows/32=16, KSPLIT=16) = 1024 blocks (~7/SM).
// -------------------------------------------------------------------------
__global__ __launch_bounds__(256) void av_kernel(
    const float* __restrict__ V, const int* __restrict__ valid_lens,
    float* __restrict__ out)
{
    __shared__ float Ps[32][17];
    __shared__ float Vs[16][68];

    const int v0 = blockIdx.x * 64;
    const int r0 = blockIdx.y * 32;          // global row (b*NQ + q)
    const int b  = r0 >> 7;
    const int kz = blockIdx.z * 64;

    if (kz >= valid_lens[b]) return;         // probs exactly zero here

    const int tid = threadIdx.x;
    const int tx = tid & 15;
    const int ty = tid >> 4;                 // 0..15

    // Ps loaders: threads 0..127, 32 rows x 16 k
    const int plr = (tid & 127) >> 2;        // 0..31
    const int plc = (tid & 3) * 4;           // 0,4,8,12
    // Vs loaders: all 256 threads, 16 rows x 64 cols
    const int vlr = tid >> 4;                // 0..15
    const int vlc = (tid & 15) * 4;          // 0..60

    const float* Vb = V + (size_t)b * NK * DV;

    float acc[2][4] = {};

    for (int k0 = kz; k0 < kz + 64; k0 += 16) {
        if (tid < 128) {
            float4 pv = *(const float4*)&g_scores[(size_t)(r0 + plr) * NK + k0 + plc];
            Ps[plr][plc + 0] = pv.x; Ps[plr][plc + 1] = pv.y;
            Ps[plr][plc + 2] = pv.z; Ps[plr][plc + 3] = pv.w;
        }
        float4 vv = *(const float4*)&Vb[(size_t)(k0 + vlr) * DV + v0 + vlc];
        Vs[vlr][vlc + 0] = vv.x; Vs[vlr][vlc + 1] = vv.y;
        Vs[vlr][vlc + 2] = vv.z; Vs[vlr][vlc + 3] = vv.w;
        __syncthreads();

        #pragma unroll
        for (int dd = 0; dd < 16; dd++) {
            float pr[2], vr[4];
            pr[0] = Ps[ty * 2 + 0][dd];
            pr[1] = Ps[ty * 2 + 1][dd];
            #pragma unroll
            for (int j = 0; j < 4; j++) vr[j] = Vs[dd][tx * 4 + j];
            #pragma unroll
            for (int i = 0; i < 2; i++)
                #pragma unroll
                for (int j = 0; j < 4; j++)
                    acc[i][j] += pr[i] * vr[j];
        }
        __syncthreads();
    }

    #pragma unroll
    for (int i = 0; i < 2; i++)
        #pragma unroll
        for (int j = 0; j < 4; j++)
            atomicAdd(&out[(size_t)(r0 + ty * 2 + i) * DV + v0 + tx * 4 + j],
                      acc[i][j]);
}

// -------------------------------------------------------------------------
extern "C" void kernel_launch(void* const* d_in, const int* in_sizes, int n_in,
                              void* d_out, int out_size)
{
    const float* queries = (const float*)d_in[0];
    const float* keys    = (const float*)d_in[1];
    const float* values  = (const float*)d_in[2];
    const int*   vlens   = (const int*)d_in[3];
    const float* Wq      = (const float*)d_in[4];
    const float* Wk      = (const float*)d_in[5];
    const float* wv      = (const float*)d_in[6];
    float* out = (float*)d_out;

    // fused q+k projection (FFMA2 experiment); dead k tiles skipped
    proj_kernel<<<dim3(4, 72), 256>>>(queries, keys, Wq, Wk, vlens);
    // scores (f32 tanh, only k < valid_len)
    scores_kernel<<<dim3(16, 16, 4), 128>>>(wv, vlens);
    // masked softmax (in place) + zero output rows
    softmax_kernel<<<512, 256>>>(vlens, out);
    // AV GEMM, split-K=16, 32-row tiles, dead chunks skipped
    av_kernel<<<dim3(4, 16, 16), 256>>>(values, vlens, out);
}